// round 2
// baseline (speedup 1.0000x reference)
#include <cuda_runtime.h>
#include <cuda_fp16.h>
#include <mma.h>
#include <cstdint>
#include <cstddef>

using namespace nvcuda;

#define NROWS 131072
#define PDIM 256
#define HID 1024
#define LN_EPS 1e-5f

// ---------------- scratch (device globals: allocation-free rule) ----------------
static __device__ __half d_H[(size_t)NROWS * HID];       // 256 MB staging: acc (pre-bias), then gelu(LN(h1))
static __device__ __half d_W1h[PDIM * HID];              // fp16 W1p
static __device__ __half d_W2h[HID * HID];               // fp16 W2p
static __device__ float  d_mu[NROWS];
static __device__ float  d_rsig[NROWS];

// ---------------- weight fp32 -> fp16 ----------------
__global__ void convert_weights_kernel(const float* __restrict__ w1,
                                       const float* __restrict__ w2) {
    int i = blockIdx.x * blockDim.x + threadIdx.x;
    if (i < PDIM * HID) d_W1h[i] = __float2half_rn(w1[i]);
    if (i < HID * HID)  d_W2h[i] = __float2half_rn(w2[i]);
}

// ---------------- GEMM tiles ----------------
// CTA tile 128x128, BK=32, 256 threads = 8 warps in 4(M) x 2(N); warp tile 32x64.
// smem: As 128 x 48 halves (12288 B), Bs 32 x 144 halves (9216 B), rowIdx 128 ints.
#define A_LDM 48
#define B_LDM 144
#define SM_A_BYTES (128 * A_LDM * 2)
#define SM_B_BYTES (32 * B_LDM * 2)
#define SM_BYTES_G1 (SM_A_BYTES + SM_B_BYTES + 128 * 4)
#define SM_BYTES_G2 (SM_A_BYTES + SM_B_BYTES)

// GEMM1: d_H[r,:] = gather(player_tab, pid)[r,:] @ W1h   (NO bias; bias folded in later)
__global__ void gemm1_kernel(const int* __restrict__ pid,
                             const float* __restrict__ ptab) {
    extern __shared__ __align__(128) char smbuf[];
    __half* As = (__half*)smbuf;
    __half* Bs = (__half*)(smbuf + SM_A_BYTES);
    int* rowIdx = (int*)(smbuf + SM_A_BYTES + SM_B_BYTES);

    const int t = threadIdx.x, lane = t & 31, warp = t >> 5;
    const int wm = warp & 3, wn = warp >> 2;
    const int rowBase = blockIdx.y * 128, colBase = blockIdx.x * 128;

    if (t < 128) rowIdx[t] = pid[rowBase + t];
    __syncthreads();

    wmma::fragment<wmma::accumulator, 16, 16, 16, float> c[2][4];
#pragma unroll
    for (int i = 0; i < 2; i++)
#pragma unroll
        for (int j = 0; j < 4; j++) wmma::fill_fragment(c[i][j], 0.0f);

    for (int k0 = 0; k0 < PDIM; k0 += 32) {
        // A: gathered fp32 -> fp16, 128x32, 4 float4 per thread
#pragma unroll
        for (int q = 0; q < 4; q++) {
            int v = t + q * 256;
            int r = v >> 3, c4 = (v & 7) * 4;
            float4 f = *(const float4*)(ptab + (size_t)rowIdx[r] * PDIM + k0 + c4);
            __half2* dst = (__half2*)(As + r * A_LDM + c4);
            dst[0] = __floats2half2_rn(f.x, f.y);
            dst[1] = __floats2half2_rn(f.z, f.w);
        }
        // B: 32x128 halves, 2 uint4 per thread
#pragma unroll
        for (int q = 0; q < 2; q++) {
            int v = t + q * 256;
            int r = v >> 4, c8 = (v & 15) * 8;
            *(uint4*)(Bs + r * B_LDM + c8) =
                *(const uint4*)(d_W1h + (size_t)(k0 + r) * HID + colBase + c8);
        }
        __syncthreads();
#pragma unroll
        for (int ks = 0; ks < 32; ks += 16) {
            wmma::fragment<wmma::matrix_a, 16, 16, 16, __half, wmma::row_major> a[2];
            wmma::fragment<wmma::matrix_b, 16, 16, 16, __half, wmma::row_major> b[4];
#pragma unroll
            for (int i = 0; i < 2; i++)
                wmma::load_matrix_sync(a[i], As + (wm * 32 + i * 16) * A_LDM + ks, A_LDM);
#pragma unroll
            for (int j = 0; j < 4; j++)
                wmma::load_matrix_sync(b[j], Bs + ks * B_LDM + wn * 64 + j * 16, B_LDM);
#pragma unroll
            for (int i = 0; i < 2; i++)
#pragma unroll
                for (int j = 0; j < 4; j++) wmma::mma_sync(c[i][j], a[i], b[j], c[i][j]);
        }
        __syncthreads();
    }

    // epilogue: per-warp fp32 staging (reuses As region), convert to fp16, store
    float* stage = (float*)smbuf + warp * 256;
    const int r = lane >> 1, c8 = (lane & 1) * 8;
#pragma unroll
    for (int i = 0; i < 2; i++)
#pragma unroll
        for (int j = 0; j < 4; j++) {
            __syncwarp();
            wmma::store_matrix_sync(stage, c[i][j], 16, wmma::mem_row_major);
            __syncwarp();
            int grow = rowBase + wm * 32 + i * 16 + r;
            int gcol = colBase + wn * 64 + j * 16 + c8;
            __align__(16) __half h8[8];
#pragma unroll
            for (int e = 0; e < 8; e++) h8[e] = __float2half_rn(stage[r * 16 + c8 + e]);
            *(uint4*)(d_H + (size_t)grow * HID + gcol) = *(uint4*)h8;
        }
}

// Row stats over h1 = d_H + b1  (mu, rsigma); one warp per row
__global__ void stats_kernel(const float* __restrict__ b1) {
    int row = blockIdx.x * 8 + (threadIdx.x >> 5);
    int lane = threadIdx.x & 31;
    const __half* hrow = d_H + (size_t)row * HID;
    float s = 0.f, ss = 0.f;
#pragma unroll
    for (int cch = 0; cch < 4; cch++) {
        int j0 = (lane + 32 * cch) * 8;
        uint4 u = *(const uint4*)(hrow + j0);
        __half2* hp = (__half2*)&u;
        float4 bA = *(const float4*)(b1 + j0);
        float4 bB = *(const float4*)(b1 + j0 + 4);
        float bb[8] = {bA.x, bA.y, bA.z, bA.w, bB.x, bB.y, bB.z, bB.w};
#pragma unroll
        for (int e = 0; e < 4; e++) {
            float2 f = __half22float2(hp[e]);
            float v0 = f.x + bb[2 * e], v1 = f.y + bb[2 * e + 1];
            s += v0 + v1;
            ss += v0 * v0 + v1 * v1;
        }
    }
#pragma unroll
    for (int o = 16; o; o >>= 1) {
        s += __shfl_xor_sync(0xffffffffu, s, o);
        ss += __shfl_xor_sync(0xffffffffu, ss, o);
    }
    if (lane == 0) {
        float mu = s * (1.0f / HID);
        float var = ss * (1.0f / HID) - mu * mu;
        d_mu[row] = mu;
        d_rsig[row] = rsqrtf(var + LN_EPS);
    }
}

// elementwise: d_H = gelu_exact( (d_H + b1 - mu) * rsig * g + beta )
__global__ void apply_ln_gelu_kernel(const float* __restrict__ b1,
                                     const float* __restrict__ g,
                                     const float* __restrict__ beta) {
    size_t i8 = ((size_t)blockIdx.x * blockDim.x + threadIdx.x) * 8;
    int row = (int)(i8 >> 10);
    int col = (int)(i8 & 1023);
    float mu = d_mu[row], rs = d_rsig[row];
    uint4 u = *(uint4*)(d_H + i8);
    __half2* hp = (__half2*)&u;
    float o[8];
#pragma unroll
    for (int e = 0; e < 4; e++) {
        float2 f = __half22float2(hp[e]);
        o[2 * e] = f.x;
        o[2 * e + 1] = f.y;
    }
#pragma unroll
    for (int e = 0; e < 8; e++) {
        float v = (o[e] + b1[col + e] - mu) * rs * g[col + e] + beta[col + e];
        o[e] = 0.5f * v * (1.0f + erff(v * 0.70710678118654752f));
    }
#pragma unroll
    for (int e = 0; e < 4; e++) hp[e] = __floats2half2_rn(o[2 * e], o[2 * e + 1]);
    *(uint4*)(d_H + i8) = u;
}

// GEMM2: out = d_H @ W2h + b2  (fp32 out)
__global__ void gemm2_kernel(const float* __restrict__ bias,
                             float* __restrict__ out) {
    extern __shared__ __align__(128) char smbuf[];
    __half* As = (__half*)smbuf;
    __half* Bs = (__half*)(smbuf + SM_A_BYTES);

    const int t = threadIdx.x, lane = t & 31, warp = t >> 5;
    const int wm = warp & 3, wn = warp >> 2;
    const int rowBase = blockIdx.y * 128, colBase = blockIdx.x * 128;

    wmma::fragment<wmma::accumulator, 16, 16, 16, float> c[2][4];
#pragma unroll
    for (int i = 0; i < 2; i++)
#pragma unroll
        for (int j = 0; j < 4; j++) wmma::fill_fragment(c[i][j], 0.0f);

    for (int k0 = 0; k0 < HID; k0 += 32) {
        // A: 128x32 halves from d_H, 2 uint4 per thread
#pragma unroll
        for (int q = 0; q < 2; q++) {
            int v = t + q * 256;
            int r = v >> 2, c8 = (v & 3) * 8;
            *(uint4*)(As + r * A_LDM + c8) =
                *(const uint4*)(d_H + (size_t)(rowBase + r) * HID + k0 + c8);
        }
#pragma unroll
        for (int q = 0; q < 2; q++) {
            int v = t + q * 256;
            int r = v >> 4, c8 = (v & 15) * 8;
            *(uint4*)(Bs + r * B_LDM + c8) =
                *(const uint4*)(d_W2h + (size_t)(k0 + r) * HID + colBase + c8);
        }
        __syncthreads();
#pragma unroll
        for (int ks = 0; ks < 32; ks += 16) {
            wmma::fragment<wmma::matrix_a, 16, 16, 16, __half, wmma::row_major> a[2];
            wmma::fragment<wmma::matrix_b, 16, 16, 16, __half, wmma::row_major> b[4];
#pragma unroll
            for (int i = 0; i < 2; i++)
                wmma::load_matrix_sync(a[i], As + (wm * 32 + i * 16) * A_LDM + ks, A_LDM);
#pragma unroll
            for (int j = 0; j < 4; j++)
                wmma::load_matrix_sync(b[j], Bs + ks * B_LDM + wn * 64 + j * 16, B_LDM);
#pragma unroll
            for (int i = 0; i < 2; i++)
#pragma unroll
                for (int j = 0; j < 4; j++) wmma::mma_sync(c[i][j], a[i], b[j], c[i][j]);
        }
        __syncthreads();
    }

    float* stage = (float*)smbuf + warp * 256;
    const int r = lane >> 1, c8 = (lane & 1) * 8;
#pragma unroll
    for (int i = 0; i < 2; i++)
#pragma unroll
        for (int j = 0; j < 4; j++) {
            __syncwarp();
            wmma::store_matrix_sync(stage, c[i][j], 16, wmma::mem_row_major);
            __syncwarp();
            int grow = rowBase + wm * 32 + i * 16 + r;
            int gcol = colBase + wn * 64 + j * 16 + c8;
            float v[8];
#pragma unroll
            for (int e = 0; e < 8; e++) v[e] = stage[r * 16 + c8 + e] + bias[gcol + e];
            float* op = out + (size_t)grow * HID + gcol;
            *(float4*)op = make_float4(v[0], v[1], v[2], v[3]);
            *(float4*)(op + 4) = make_float4(v[4], v[5], v[6], v[7]);
        }
}

// Sparse fallback: one CTA per row; does real work only where pid==0 (~3 rows)
__global__ void fallback_kernel(const int* __restrict__ pid,
                                const int* __restrict__ tid_,
                                const int* __restrict__ rid,
                                const float* __restrict__ team_tab,
                                const float* __restrict__ role_tab,
                                const float* __restrict__ W1f,
                                const float* __restrict__ b1f,
                                const float* __restrict__ gf,
                                const float* __restrict__ bf,
                                const float* __restrict__ W2f,
                                const float* __restrict__ b2f,
                                float* __restrict__ out) {
    int row = blockIdx.x;
    if (pid[row] != 0) return;

    __shared__ float in[192];
    __shared__ float hs[1024];
    __shared__ float red[32];
    int t = threadIdx.x;
    int tt = tid_[row], rr = rid[row];
    if (t < 128) in[t] = team_tab[tt * 128 + t];
    else if (t < 192) in[t] = role_tab[rr * 64 + (t - 128)];
    __syncthreads();

    float hv[4];
    float s = 0.f, ss = 0.f;
#pragma unroll
    for (int q = 0; q < 4; q++) {
        int j = t + q * 256;
        float acc = b1f[j];
#pragma unroll 8
        for (int k = 0; k < 192; k++) acc += in[k] * W1f[k * 1024 + j];
        hv[q] = acc;
        s += acc;
        ss += acc * acc;
    }
#pragma unroll
    for (int o = 16; o; o >>= 1) {
        s += __shfl_xor_sync(0xffffffffu, s, o);
        ss += __shfl_xor_sync(0xffffffffu, ss, o);
    }
    if ((t & 31) == 0) { red[t >> 5] = s; red[8 + (t >> 5)] = ss; }
    __syncthreads();
    if (t == 0) {
        float S = 0.f, SS = 0.f;
        for (int w = 0; w < 8; w++) { S += red[w]; SS += red[8 + w]; }
        float mu = S / 1024.0f;
        float var = SS / 1024.0f - mu * mu;
        red[16] = mu;
        red[17] = rsqrtf(var + LN_EPS);
    }
    __syncthreads();
    float mu = red[16], rs = red[17];
#pragma unroll
    for (int q = 0; q < 4; q++) {
        int j = t + q * 256;
        float v = (hv[q] - mu) * rs * gf[j] + bf[j];
        hs[j] = 0.5f * v * (1.0f + erff(v * 0.70710678118654752f));
    }
    __syncthreads();
#pragma unroll
    for (int q = 0; q < 4; q++) {
        int j = t + q * 256;
        float acc = b2f[j];
        for (int k = 0; k < 1024; k++) acc += hs[k] * W2f[k * 1024 + j];
        out[(size_t)row * 1024 + j] = acc;
    }
}

// ---------------- launch ----------------
extern "C" void kernel_launch(void* const* d_in, const int* in_sizes, int n_in,
                              void* d_out, int out_size) {
    const int* pid = (const int*)d_in[0];
    const int* tid = (const int*)d_in[1];
    const int* rid = (const int*)d_in[2];
    const float* ptab = (const float*)d_in[3];
    const float* ttab = (const float*)d_in[4];
    const float* rtab = (const float*)d_in[5];
    const float* W1p = (const float*)d_in[6];
    const float* b1p = (const float*)d_in[7];
    const float* gp  = (const float*)d_in[8];
    const float* bp  = (const float*)d_in[9];
    const float* W2p = (const float*)d_in[10];
    const float* b2p = (const float*)d_in[11];
    const float* W1f = (const float*)d_in[12];
    const float* b1f = (const float*)d_in[13];
    const float* gf  = (const float*)d_in[14];
    const float* bf  = (const float*)d_in[15];
    const float* W2f = (const float*)d_in[16];
    const float* b2f = (const float*)d_in[17];
    float* out = (float*)d_out;

    convert_weights_kernel<<<(HID * HID + 255) / 256, 256>>>(W1p, W2p);
    gemm1_kernel<<<dim3(HID / 128, NROWS / 128), 256, SM_BYTES_G1>>>(pid, ptab);
    stats_kernel<<<NROWS / 8, 256>>>(b1p);
    apply_ln_gelu_kernel<<<(NROWS * (HID / 8)) / 256, 256>>>(b1p, gp, bp);
    gemm2_kernel<<<dim3(HID / 128, NROWS / 128), 256, SM_BYTES_G2>>>(b2p, out);
    fallback_kernel<<<NROWS, 256>>>(pid, tid, rid, ttab, rtab,
                                    W1f, b1f, gf, bf, W2f, b2f, out);
}

// round 4
// speedup vs baseline: 1.6951x; 1.6951x over previous
#include <cuda_runtime.h>
#include <cuda_fp16.h>
#include <mma.h>
#include <cstdint>
#include <cstddef>

using namespace nvcuda;

#define NROWS 131072
#define PDIM 256
#define HID 1024
#define LN_EPS 1e-5f

// ---------------- scratch (device globals; allocation-free rule) ----------------
static __device__ __half d_H[(size_t)NROWS * HID];    // 256MB: GEMM1 out -> LN/gelu in-place
static __device__ __half d_X[(size_t)NROWS * PDIM];   // 64MB: gathered player embeddings fp16
static __device__ __half d_W1h[PDIM * HID];           // W1p fp16 [K][N]
static __device__ __half d_W2h[HID * HID];            // W2p fp16 [K][N]

__device__ __forceinline__ uint32_t smem_u32(const void* p) {
    uint32_t a;
    asm("{ .reg .u64 t; cvta.to.shared.u64 t, %1; cvt.u32.u64 %0, t; }" : "=r"(a) : "l"(p));
    return a;
}
#define CP16(sm, gp)  asm volatile("cp.async.cg.shared.global [%0], [%1], 16;" :: "r"(sm), "l"(gp))
#define CP_COMMIT()   asm volatile("cp.async.commit_group;" ::: "memory")
#define CP_WAIT1()    asm volatile("cp.async.wait_group 1;" ::: "memory")

// ---------------- GEMM config ----------------
#define BM 128
#define BN 128
#define BK 64
#define STAGES 3
#define A_LDM 72            // 64 + 8 halves pad
#define B_LDM 136           // 128 + 8 halves pad
#define A_STAGE_BYTES (BM * A_LDM * 2)                 // 18432
#define B_STAGE_BYTES (BK * B_LDM * 2)                 // 17408
#define SM_A_OFF(s) ((s) * A_STAGE_BYTES)
#define SM_B_OFF(s) (STAGES * A_STAGE_BYTES + (s) * B_STAGE_BYTES)
#define SMEM_GEMM (STAGES * (A_STAGE_BYTES + B_STAGE_BYTES))   // 107520 B

template <int K>
__device__ __forceinline__ void load_stage(uint32_t smb, char* sm, int s, int kb,
                                           const __half* __restrict__ A,
                                           const __half* __restrict__ B,
                                           int rowBase, int colBase, int t) {
    const int k0 = kb * BK;
    const uint32_t sa = smb + SM_A_OFF(s);
#pragma unroll
    for (int q = 0; q < 4; q++) {
        int idx = q * 256 + t;
        int r = idx >> 3, c8 = idx & 7;
        const __half* gp = A + (size_t)(rowBase + r) * K + k0 + c8 * 8;
        CP16(sa + r * (A_LDM * 2) + c8 * 16, gp);
    }
    const uint32_t sb = smb + SM_B_OFF(s);
#pragma unroll
    for (int q = 0; q < 4; q++) {
        int idx = q * 256 + t;
        int r = idx >> 4, c8 = idx & 15;
        const __half* gp = B + (size_t)(k0 + r) * HID + colBase + c8 * 8;
        CP16(sb + r * (B_LDM * 2) + c8 * 16, gp);
    }
}

// C[128x128] = A[BMxK] @ B[KxBN]; BIASOUT ? fp32 out + bias : fp16 to d_H
template <int K, bool BIASOUT>
__global__ __launch_bounds__(256, 2) void hgemm_kernel(const __half* __restrict__ A,
                                                       const __half* __restrict__ B,
                                                       const float* __restrict__ bias,
                                                       float* __restrict__ outF,
                                                       __half* __restrict__ outH) {
    extern __shared__ __align__(1024) char sm[];
    const uint32_t smb = smem_u32(sm);
    const int t = threadIdx.x, lane = t & 31, warp = t >> 5;
    const int wm = warp & 3, wn = warp >> 2;
    const int rowBase = blockIdx.y * BM, colBase = blockIdx.x * BN;
    constexpr int KB = K / BK;

    wmma::fragment<wmma::accumulator, 16, 16, 16, float> c[2][4];
#pragma unroll
    for (int i = 0; i < 2; i++)
#pragma unroll
        for (int j = 0; j < 4; j++) wmma::fill_fragment(c[i][j], 0.0f);

    // prologue: stages 0..STAGES-2
#pragma unroll
    for (int s = 0; s < STAGES - 1; s++) {
        load_stage<K>(smb, sm, s, s, A, B, rowBase, colBase, t);
        CP_COMMIT();
    }

    for (int kb = 0; kb < KB; kb++) {
        CP_WAIT1();            // stage kb resident
        __syncthreads();       // also orders prev compute before next issue
        const int nxt = kb + STAGES - 1;
        if (nxt < KB) load_stage<K>(smb, sm, nxt % STAGES, nxt, A, B, rowBase, colBase, t);
        CP_COMMIT();           // empty-commit at tail keeps group count uniform

        const __half* Asb = (const __half*)(sm + SM_A_OFF(kb % STAGES));
        const __half* Bsb = (const __half*)(sm + SM_B_OFF(kb % STAGES));
#pragma unroll
        for (int ks = 0; ks < BK; ks += 16) {
            wmma::fragment<wmma::matrix_a, 16, 16, 16, __half, wmma::row_major> a[2];
            wmma::fragment<wmma::matrix_b, 16, 16, 16, __half, wmma::row_major> b[4];
#pragma unroll
            for (int i = 0; i < 2; i++)
                wmma::load_matrix_sync(a[i], Asb + (wm * 32 + i * 16) * A_LDM + ks, A_LDM);
#pragma unroll
            for (int j = 0; j < 4; j++)
                wmma::load_matrix_sync(b[j], Bsb + ks * B_LDM + wn * 64 + j * 16, B_LDM);
#pragma unroll
            for (int i = 0; i < 2; i++)
#pragma unroll
                for (int j = 0; j < 4; j++) wmma::mma_sync(c[i][j], a[i], b[j], c[i][j]);
        }
    }
    __syncthreads();   // smem free for epilogue staging

    float* stage = (float*)sm + warp * 256;
    const int r = lane >> 1, c8 = (lane & 1) * 8;
#pragma unroll
    for (int i = 0; i < 2; i++)
#pragma unroll
        for (int j = 0; j < 4; j++) {
            __syncwarp();
            wmma::store_matrix_sync(stage, c[i][j], 16, wmma::mem_row_major);
            __syncwarp();
            const int grow = rowBase + wm * 32 + i * 16 + r;
            const int gcol = colBase + wn * 64 + j * 16 + c8;
            if (BIASOUT) {
                float v[8];
#pragma unroll
                for (int e = 0; e < 8; e++) v[e] = stage[r * 16 + c8 + e] + bias[gcol + e];
                float* op = outF + (size_t)grow * HID + gcol;
                *(float4*)op = make_float4(v[0], v[1], v[2], v[3]);
                *(float4*)(op + 4) = make_float4(v[4], v[5], v[6], v[7]);
            } else {
                __align__(16) __half h8[8];
#pragma unroll
                for (int e = 0; e < 8; e++) h8[e] = __float2half_rn(stage[r * 16 + c8 + e]);
                *(uint4*)(outH + (size_t)grow * HID + gcol) = *(uint4*)h8;
            }
        }
}

// ---------------- gather + fp32->fp16 convert: d_X[r,:] = half(ptab[pid[r],:]) ----------------
__global__ __launch_bounds__(256) void gather_kernel(const int* __restrict__ pid,
                                                     const float* __restrict__ ptab) {
    const size_t gid = (size_t)blockIdx.x * 256 + threadIdx.x;   // NROWS*32 threads
    const int row = (int)(gid >> 5), ch = (int)(gid & 31);
    const float* gp = ptab + (size_t)pid[row] * PDIM + ch * 8;
    float4 f0 = *(const float4*)gp;
    float4 f1 = *(const float4*)(gp + 4);
    __align__(16) __half2 h[4];
    h[0] = __floats2half2_rn(f0.x, f0.y);
    h[1] = __floats2half2_rn(f0.z, f0.w);
    h[2] = __floats2half2_rn(f1.x, f1.y);
    h[3] = __floats2half2_rn(f1.z, f1.w);
    *(uint4*)(d_X + (size_t)row * PDIM + ch * 8) = *(uint4*)h;
}

// ---------------- weight fp32 -> fp16 (no transpose; row-major [K][N]) ----------------
__global__ void convw_kernel(const float* __restrict__ w1, const float* __restrict__ w2) {
    const int i8 = blockIdx.x * 256 + threadIdx.x;   // 8 elems each
    if (i8 < PDIM * HID / 8) {
        const float* gp = w1 + i8 * 8;
        float4 f0 = *(const float4*)gp, f1 = *(const float4*)(gp + 4);
        __align__(16) __half2 h[4];
        h[0] = __floats2half2_rn(f0.x, f0.y); h[1] = __floats2half2_rn(f0.z, f0.w);
        h[2] = __floats2half2_rn(f1.x, f1.y); h[3] = __floats2half2_rn(f1.z, f1.w);
        *(uint4*)(d_W1h + i8 * 8) = *(uint4*)h;
    }
    if (i8 < HID * HID / 8) {
        const float* gp = w2 + i8 * 8;
        float4 f0 = *(const float4*)gp, f1 = *(const float4*)(gp + 4);
        __align__(16) __half2 h[4];
        h[0] = __floats2half2_rn(f0.x, f0.y); h[1] = __floats2half2_rn(f0.z, f0.w);
        h[2] = __floats2half2_rn(f1.x, f1.y); h[3] = __floats2half2_rn(f1.z, f1.w);
        *(uint4*)(d_W2h + i8 * 8) = *(uint4*)h;
    }
}

// ---------------- fused stats + LN + gelu, in-place on d_H ----------------
__global__ __launch_bounds__(256) void ln_gelu_kernel(const float* __restrict__ b1,
                                                      const float* __restrict__ g,
                                                      const float* __restrict__ beta) {
    __shared__ float sb[1024], sg[1024], se[1024];
    const int t = threadIdx.x;
#pragma unroll
    for (int i = 0; i < 4; i++) {
        int j = t + i * 256;
        sb[j] = b1[j]; sg[j] = g[j]; se[j] = beta[j];
    }
    __syncthreads();
    const int row = blockIdx.x * 8 + (t >> 5);
    const int lane = t & 31;
    __half* hrow = d_H + (size_t)row * HID;

    uint4 u[4];
    float v[32];
    float s = 0.f, ss = 0.f;
#pragma unroll
    for (int cc = 0; cc < 4; cc++) {
        u[cc] = *(uint4*)(hrow + cc * 256 + lane * 8);
        __half2* hp = (__half2*)&u[cc];
#pragma unroll
        for (int e = 0; e < 4; e++) {
            int col = cc * 256 + lane * 8 + 2 * e;
            float2 f = __half22float2(hp[e]);
            float a0 = f.x + sb[col], a1 = f.y + sb[col + 1];
            v[cc * 8 + 2 * e] = a0;
            v[cc * 8 + 2 * e + 1] = a1;
            s += a0 + a1;
            ss += a0 * a0 + a1 * a1;
        }
    }
#pragma unroll
    for (int o = 16; o; o >>= 1) {
        s += __shfl_xor_sync(0xffffffffu, s, o);
        ss += __shfl_xor_sync(0xffffffffu, ss, o);
    }
    float mu = s * (1.0f / HID);
    float rs = rsqrtf(ss * (1.0f / HID) - mu * mu + LN_EPS);
#pragma unroll
    for (int cc = 0; cc < 4; cc++) {
        __half2* hp = (__half2*)&u[cc];
#pragma unroll
        for (int e = 0; e < 4; e++) {
            int col = cc * 256 + lane * 8 + 2 * e;
            float x0 = (v[cc * 8 + 2 * e] - mu) * rs * sg[col] + se[col];
            float x1 = (v[cc * 8 + 2 * e + 1] - mu) * rs * sg[col + 1] + se[col + 1];
            x0 = 0.5f * x0 * (1.0f + erff(x0 * 0.70710678118654752f));
            x1 = 0.5f * x1 * (1.0f + erff(x1 * 0.70710678118654752f));
            hp[e] = __floats2half2_rn(x0, x1);
        }
        *(uint4*)(hrow + cc * 256 + lane * 8) = u[cc];
    }
}

// ---------------- sparse fallback (pid==0, ~3 rows) ----------------
__global__ void fallback_kernel(const int* __restrict__ pid, const int* __restrict__ tid_,
                                const int* __restrict__ rid, const float* __restrict__ team_tab,
                                const float* __restrict__ role_tab, const float* __restrict__ W1f,
                                const float* __restrict__ b1f, const float* __restrict__ gf,
                                const float* __restrict__ bf, const float* __restrict__ W2f,
                                const float* __restrict__ b2f, float* __restrict__ out) {
    int row = blockIdx.x;
    if (pid[row] != 0) return;
    __shared__ float in[192];
    __shared__ float hs[1024];
    __shared__ float red[32];
    int t = threadIdx.x;
    int tt = tid_[row], rr = rid[row];
    if (t < 128) in[t] = team_tab[tt * 128 + t];
    else if (t < 192) in[t] = role_tab[rr * 64 + (t - 128)];
    __syncthreads();
    float hv[4], s = 0.f, ss = 0.f;
#pragma unroll
    for (int q = 0; q < 4; q++) {
        int j = t + q * 256;
        float acc = b1f[j];
#pragma unroll 8
        for (int k = 0; k < 192; k++) acc += in[k] * W1f[k * 1024 + j];
        hv[q] = acc; s += acc; ss += acc * acc;
    }
#pragma unroll
    for (int o = 16; o; o >>= 1) {
        s += __shfl_xor_sync(0xffffffffu, s, o);
        ss += __shfl_xor_sync(0xffffffffu, ss, o);
    }
    if ((t & 31) == 0) { red[t >> 5] = s; red[8 + (t >> 5)] = ss; }
    __syncthreads();
    if (t == 0) {
        float S = 0.f, SS = 0.f;
        for (int w = 0; w < 8; w++) { S += red[w]; SS += red[8 + w]; }
        float mu = S / 1024.0f;
        red[16] = mu;
        red[17] = rsqrtf(SS / 1024.0f - mu * mu + LN_EPS);
    }
    __syncthreads();
    float mu = red[16], rs = red[17];
#pragma unroll
    for (int q = 0; q < 4; q++) {
        int j = t + q * 256;
        float v = (hv[q] - mu) * rs * gf[j] + bf[j];
        hs[j] = 0.5f * v * (1.0f + erff(v * 0.70710678118654752f));
    }
    __syncthreads();
#pragma unroll
    for (int q = 0; q < 4; q++) {
        int j = t + q * 256;
        float acc = b2f[j];
        for (int k = 0; k < 1024; k++) acc += hs[k] * W2f[k * 1024 + j];
        out[(size_t)row * 1024 + j] = acc;
    }
}

// ---------------- launch ----------------
extern "C" void kernel_launch(void* const* d_in, const int* in_sizes, int n_in,
                              void* d_out, int out_size) {
    const int* pid = (const int*)d_in[0];
    const int* tid = (const int*)d_in[1];
    const int* rid = (const int*)d_in[2];
    const float* ptab = (const float*)d_in[3];
    const float* ttab = (const float*)d_in[4];
    const float* rtab = (const float*)d_in[5];
    const float* W1p = (const float*)d_in[6];
    const float* b1p = (const float*)d_in[7];
    const float* gp  = (const float*)d_in[8];
    const float* bp  = (const float*)d_in[9];
    const float* W2p = (const float*)d_in[10];
    const float* b2p = (const float*)d_in[11];
    const float* W1f = (const float*)d_in[12];
    const float* b1f = (const float*)d_in[13];
    const float* gf  = (const float*)d_in[14];
    const float* bf  = (const float*)d_in[15];
    const float* W2f = (const float*)d_in[16];
    const float* b2f = (const float*)d_in[17];
    float* out = (float*)d_out;

    cudaFuncSetAttribute(hgemm_kernel<PDIM, false>,
                         cudaFuncAttributeMaxDynamicSharedMemorySize, SMEM_GEMM);
    cudaFuncSetAttribute(hgemm_kernel<HID, true>,
                         cudaFuncAttributeMaxDynamicSharedMemorySize, SMEM_GEMM);

    __half *x, *h, *w1h, *w2h;
    cudaGetSymbolAddress((void**)&x, d_X);
    cudaGetSymbolAddress((void**)&h, d_H);
    cudaGetSymbolAddress((void**)&w1h, d_W1h);
    cudaGetSymbolAddress((void**)&w2h, d_W2h);

    convw_kernel<<<HID * HID / 8 / 256, 256>>>(W1p, W2p);
    gather_kernel<<<NROWS * 32 / 256, 256>>>(pid, ptab);
    hgemm_kernel<PDIM, false><<<dim3(HID / BN, NROWS / BM), 256, SMEM_GEMM>>>(
        x, w1h, nullptr, nullptr, h);
    ln_gelu_kernel<<<NROWS / 8, 256>>>(b1p, gp, bp);
    hgemm_kernel<HID, true><<<dim3(HID / BN, NROWS / BM), 256, SMEM_GEMM>>>(
        h, w2h, b2p, out, nullptr);
    fallback_kernel<<<NROWS, 256>>>(pid, tid, rid, ttab, rtab,
                                    W1f, b1f, gf, bf, W2f, b2f, out);
}